// round 16
// baseline (speedup 1.0000x reference)
#include <cuda_runtime.h>
#include <cuda_fp16.h>
#include <math.h>
#include <stdint.h>

#define Tc   336
#define BNT  16384
#define Fc   720
#define Nch  128
#define Bc   128
#define KC   48          // k-cols per smem stage
#define NSTG 7           // 336/48
#define RSTR 112         // smem row stride bytes (48 fp16 = 96B + 16 pad; 112/16=7 coprime 8)
#define NTHR 512

// ---------------- scratch globals ----------------
__device__ float g_ms[BNT*8];
__device__ float g_spmu[BNT*4];
__device__ float g_spsg[BNT*4];
__device__ float g_w[BNT*4];
__device__ float g_coef[BNT*8];
__device__ float g_S[64 + 4*Fc];

__device__ __forceinline__ float softplus_f(float x){
    return fmaxf(x,0.f) + log1pf(expf(-fabsf(x)));
}
__device__ __forceinline__ uint32_t su32(const void* p){
    uint32_t a;
    asm("{ .reg .u64 t; cvta.to.shared.u64 t, %1; cvt.u32.u64 %0, t; }" : "=r"(a) : "l"(p));
    return a;
}

#define LDSM4(r, a) asm volatile( \
    "ldmatrix.sync.aligned.m8n8.x4.shared.b16 {%0,%1,%2,%3}, [%4];" \
    : "=r"((r)[0]), "=r"((r)[1]), "=r"((r)[2]), "=r"((r)[3]) : "r"(a))
#define MMAH(c, a, b) asm volatile( \
    "mma.sync.aligned.m16n8k16.row.col.f32.f16.f16.f32 " \
    "{%0,%1,%2,%3}, {%4,%5,%6,%7}, {%8,%9}, {%0,%1,%2,%3};" \
    : "+f"((c)[0]), "+f"((c)[1]), "+f"((c)[2]), "+f"((c)[3]) \
    : "r"((a)[0]), "r"((a)[1]), "r"((a)[2]), "r"((a)[3]), "r"((b)[0]), "r"((b)[1]))

__device__ __forceinline__ uint2 cvt_h4(float4 v){
    __half2 a = __floats2half2_rn(v.x, v.y);
    __half2 b = __floats2half2_rn(v.z, v.w);
    return make_uint2(*(uint32_t*)&a, *(uint32_t*)&b);
}

// =====================================================================
// 512-thread (16-warp, 4x4 grid, 32x32 warp tile) double-buffered fp16
// mma.sync GEMM with register-fragment double buffering + fused epilogue.
//   acc[m,n] = A[m,:].W1[n,:]  (K=336)
//   h = relu(b1[n] + smu[m]*S[n] + ssg[m]*acc)
//   WMODE 0: out[m*ostride+ooff+d] = sum_n h*W2[d,n]
//   WMODE 1: logits -> softmax over groups of 4 rows -> out (g_w)
// =====================================================================
template<int NTILE, int RT, int WMODE>
__device__ __forceinline__ void gemm_core(
    const float* __restrict__ A, int lda,
    const float* __restrict__ W1, int Ncols, int n_nt,
    const float* __restrict__ b1, const float* __restrict__ S,
    const float* __restrict__ spmu, const float* __restrict__ spsg,
    int sp_mul, int sp_add,
    const float* __restrict__ W2, int R,
    float* __restrict__ outp, int ostride, int ooff,
    int m0, char* smem)
{
    constexpr int ATILE = 128*RSTR;                  // fp16 A tile bytes
    constexpr int BTILE = NTILE*RSTR;
    constexpr int BUFSZ = ATILE + BTILE;
    constexpr int NB4   = (NTILE*12 + NTHR-1)/NTHR;  // B float4 per thread per stage
    constexpr bool BGUARD = (NTILE*12 % NTHR) != 0;
    constexpr int NJ    = NTILE/32;                  // n8 tiles per warp (4x4 grid)
    constexpr int NPW   = NTILE/4;                   // N cols per warp

    const int tid = threadIdx.x;
    const int wid = tid >> 5, lane = tid & 31;
    const int g = lane >> 2, l = lane & 3;
    const int wm = wid >> 2, wn = wid & 3;           // 4x4 warp grid; warp tile 32 x NPW
    const uint32_t sb = su32(smem);
    float* stg = (float*)(smem + 2*BUFSZ);
    float* red = (float*)(smem + 2*BUFSZ + (2+RT)*NTILE*4);

    if (tid < 128) ((float4*)red)[tid] = make_float4(0.f,0.f,0.f,0.f);

    float part[4][RT];
    #pragma unroll
    for (int s = 0; s < 4; s++)
        #pragma unroll
        for (int d = 0; d < RT; d++) part[s][d] = 0.f;

    float4 pa[3], pb[NB4];

    auto ldgA = [&](int kc){
        #pragma unroll
        for (int it = 0; it < 3; it++){
            int q = tid + it*NTHR; int r = q/12, cq = q - r*12;
            pa[it] = *(const float4*)(A + (long)(m0 + r)*lda + kc*KC + cq*4);
        }
    };
    auto ldgB = [&](int nt, int kc){
        #pragma unroll
        for (int it = 0; it < NB4; it++){
            int q = tid + it*NTHR;
            if (!BGUARD || q < NTILE*12){
                int n = q/12, cq = q - n*12;
                int gn = nt*NTILE + n;
                pb[it] = (gn < Ncols) ? *(const float4*)(W1 + (long)gn*Tc + kc*KC + cq*4)
                                      : make_float4(0.f,0.f,0.f,0.f);
            }
        }
    };
    auto sts = [&](int buf){
        char* bb = smem + buf*BUFSZ;
        #pragma unroll
        for (int it = 0; it < 3; it++){
            int q = tid + it*NTHR; int r = q/12, cq = q - r*12;
            *(uint2*)(bb + r*RSTR + cq*8) = cvt_h4(pa[it]);
        }
        #pragma unroll
        for (int it = 0; it < NB4; it++){
            int q = tid + it*NTHR;
            if (!BGUARD || q < NTILE*12){
                int n = q/12, cq = q - n*12;
                *(uint2*)(bb + ATILE + n*RSTR + cq*8) = cvt_h4(pb[it]);
            }
        }
    };

    // register fragment double buffers
    uint32_t fa[2][2][4];
    uint32_t fb[2][NJ][2];

    auto frag_ld = [&](uint32_t base, int ks, int p){
        #pragma unroll
        for (int i = 0; i < 2; i++){
            int row = wm*32 + i*16 + (lane & 15);
            uint32_t ad = base + row*RSTR + ks*32 + ((lane>>4)<<4);
            LDSM4(fa[p][i], ad);
        }
        #pragma unroll
        for (int pq = 0; pq < NJ/2; pq++){
            int rowb = wn*NPW + pq*16 + ((lane>>4)<<3) + (lane & 7);
            uint32_t ad = base + ATILE + rowb*RSTR + ks*32 + (((lane>>3)&1)<<4);
            uint32_t t[4];
            LDSM4(t, ad);
            fb[p][2*pq][0]=t[0]; fb[p][2*pq][1]=t[1];
            fb[p][2*pq+1][0]=t[2]; fb[p][2*pq+1][1]=t[3];
        }
    };

    for (int nt = 0; nt < n_nt; nt++){
        __syncthreads();   // stg reuse + buf0 reuse safety
        // staging: b1 / S / W2 rows for this n-tile
        for (int idx = tid; idx < NTILE*(2+RT); idx += NTHR){
            int n = idx % NTILE, row = idx / NTILE;
            int gn = nt*NTILE + n;
            float v = 0.f;
            if (gn < Ncols){
                if (row == 0)           v = b1[gn];
                else if (row == 1)      v = (S != nullptr) ? S[gn] : 0.f;
                else if (row - 2 < R)   v = W2[(row-2)*Ncols + gn];
            }
            stg[row*NTILE + n] = v;
        }

        float acc[2][NJ][4];
        #pragma unroll
        for (int i = 0; i < 2; i++)
            #pragma unroll
            for (int j = 0; j < NJ; j++)
                #pragma unroll
                for (int e = 0; e < 4; e++) acc[i][j][e] = 0.f;

        ldgA(0); ldgB(nt, 0);
        sts(0);
        __syncthreads();

        auto frag_mma = [&](int p){
            #pragma unroll
            for (int i = 0; i < 2; i++)
                #pragma unroll
                for (int j = 0; j < NJ; j++)
                    MMAH(acc[i][j], fa[p][i], fb[p][j]);
        };

        for (int kc = 0; kc < NSTG; kc++){
            const uint32_t base = sb + (kc & 1)*BUFSZ;
            const bool more = (kc + 1 < NSTG);
            if (more){ ldgA(kc+1); ldgB(nt, kc+1); }
            frag_ld(base, 0, 0);      // ks0 -> buf0
            frag_ld(base, 1, 1);      // ks1 -> buf1 (overlaps nothing yet)
            frag_mma(0);              // mma ks0 (covers ks1 ldsm)
            if (more) sts((kc+1) & 1);
            frag_ld(base, 2, 0);      // ks2 -> buf0 (covered by mma ks1)
            frag_mma(1);              // mma ks1
            frag_mma(0);              // mma ks2 (frags already in buf0)
            __syncthreads();
        }

        // ---- epilogue: relu + affine + partial n-reduction ----
        float smu4[4], ssg4[4];
        #pragma unroll
        for (int s = 0; s < 4; s++){
            if (spmu != nullptr){
                int row = m0 + wm*32 + (s>>1)*16 + g + (s&1)*8;
                smu4[s] = spmu[row*sp_mul + sp_add];
                ssg4[s] = spsg[row*sp_mul + sp_add];
            } else { smu4[s] = 0.f; ssg4[s] = 1.f; }
        }
        #pragma unroll
        for (int i = 0; i < 2; i++)
            #pragma unroll
            for (int j = 0; j < NJ; j++)
                #pragma unroll
                for (int e = 0; e < 4; e++){
                    int nl = wn*NPW + j*8 + 2*l + (e&1);
                    int s  = i*2 + (e>>1);
                    float hv = fmaxf(stg[nl] + smu4[s]*stg[NTILE+nl] + ssg4[s]*acc[i][j][e], 0.f);
                    #pragma unroll
                    for (int d = 0; d < RT; d++)
                        part[s][d] += stg[(2+d)*NTILE + nl] * hv;
                }
    }

    // cross-lane (l) reduce, then cross-warp via smem atomics
    #pragma unroll
    for (int s = 0; s < 4; s++)
        #pragma unroll
        for (int d = 0; d < RT; d++){
            float v = part[s][d];
            v += __shfl_xor_sync(0xffffffffu, v, 1);
            v += __shfl_xor_sync(0xffffffffu, v, 2);
            part[s][d] = v;
        }
    if (l == 0){
        #pragma unroll
        for (int s = 0; s < 4; s++){
            int rl = wm*32 + (s>>1)*16 + g + (s&1)*8;
            #pragma unroll
            for (int d = 0; d < RT; d++)
                if (d < R) atomicAdd(&red[rl*4 + d], part[s][d]);
        }
    }
    __syncthreads();
    if (WMODE == 0){
        if (tid < 128)
            for (int d = 0; d < R; d++)
                outp[(long)(m0 + tid)*ostride + ooff + d] = red[tid*4 + d];
    } else {
        if (tid < 32){
            float lg0 = red[(tid*4+0)*4], lg1 = red[(tid*4+1)*4];
            float lg2 = red[(tid*4+2)*4], lg3 = red[(tid*4+3)*4];
            float m = fmaxf(fmaxf(lg0,lg1), fmaxf(lg2,lg3));
            float e0 = expf(lg0-m), e1 = expf(lg1-m), e2 = expf(lg2-m), e3 = expf(lg3-m);
            float inv = 1.f/(e0+e1+e2+e3);
            outp[m0 + tid*4 + 0] = e0*inv; outp[m0 + tid*4 + 1] = e1*inv;
            outp[m0 + tid*4 + 2] = e2*inv; outp[m0 + tid*4 + 3] = e3*inv;
        }
    }
}

// ---------------- kernels ----------------
struct MainArgs {
    const float *wgW1, *wgb1, *wgW2, *Sp, *spm, *sps;
    const float *fW1[4], *fb1[4], *fW2[4];
    float *gw, *cf;
};

__global__ __launch_bounds__(NTHR,1) void main_k(const float* __restrict__ eps, MainArgs a)
{
    extern __shared__ char smem[];
    int bid = blockIdx.x;
    if (bid < 512){   // fitters first: heavy CTAs start in wave 1
        int i  = bid >> 7;
        int m0 = (bid & 127)*128;
        int R   = (i == 2) ? 3 : ((i == 1) ? 2 : 1);
        int off = (i == 0) ? 0 : (i == 1) ? 1 : (i == 2) ? 3 : 6;
        gemm_core<128,3,0>(eps + i*Tc, 4*Tc, a.fW1[i], Fc, 6, a.fb1[i],
                           a.Sp + 64 + i*Fc, a.spm, a.sps, 4, i,
                           a.fW2[i], R, a.cf, 8, off, m0, smem);
    } else {
        int m0 = (bid - 512)*128;
        gemm_core<64,1,1>(eps, Tc, a.wgW1, 64, 1, a.wgb1, a.Sp,
                          a.spm, a.sps, 1, 0, a.wgW2, 1,
                          a.gw, 1, 0, m0, smem);
    }
}

__global__ __launch_bounds__(NTHR,1) void musig_k(
    const float* __restrict__ x,
    const float* muW1, const float* mub1, const float* muW2,
    const float* sgW1, const float* sgb1, const float* sgW2, float* ms)
{
    extern __shared__ char smem[];
    if (blockIdx.y == 0)
        gemm_core<64,4,0>(x, Tc, muW1, 64, 1, mub1, nullptr, nullptr, nullptr, 0, 0,
                          muW2, 4, ms, 8, 0, blockIdx.x*128, smem);
    else
        gemm_core<64,4,0>(x, Tc, sgW1, 64, 1, sgb1, nullptr, nullptr, nullptr, 0, 0,
                          sgW2, 4, ms, 8, 4, blockIdx.x*128, smem);
}

struct RowArgs { const float *wg, *f[4]; };
__global__ void rowsum_all(RowArgs ra, float* __restrict__ S)
{
    int r = (blockIdx.x * blockDim.x + threadIdx.x) >> 5;
    int lane = threadIdx.x & 31;
    if (r >= 64 + 4*Fc) return;
    const float* row;
    if (r < 64) row = ra.wg + (long)r*Tc;
    else { int i = (r-64)/Fc, rr = (r-64) - i*Fc; row = ra.f[i] + (long)rr*Tc; }
    float s = 0.f;
    for (int j = lane; j < Tc; j += 32) s += row[j];
    #pragma unroll
    for (int o = 16; o; o >>= 1) s += __shfl_xor_sync(0xffffffffu, s, o);
    if (lane == 0) S[r] = s;
}

__global__ void softplus_k(const float* __restrict__ mub2, const float* __restrict__ sgb2){
    int i = blockIdx.x*256 + threadIdx.x;
    if (i >= BNT*4) return;
    int row = i >> 2, k = i & 3;
    g_spmu[i] = softplus_f(g_ms[row*8 + k]     + mub2[k]);
    g_spsg[i] = softplus_f(g_ms[row*8 + 4 + k] + sgb2[k]);
}

#define FCHUNK 48
__global__ void final_kernel(float* __restrict__ out,
                             const float* __restrict__ b2_0, const float* __restrict__ b2_1,
                             const float* __restrict__ b2_2, const float* __restrict__ b2_3){
    int b  = blockIdx.y;
    int f0 = blockIdx.x * FCHUNK;
    int n  = threadIdx.x;
    int bn = b * Nch + n;
    float w0 = g_w[bn*4+0], w1 = g_w[bn*4+1], w2 = g_w[bn*4+2], w3 = g_w[bn*4+3];
    float c0 = g_coef[bn*8+0] + b2_0[0];
    float c1 = g_coef[bn*8+1] + b2_1[0], c2 = g_coef[bn*8+2] + b2_1[1];
    float c3 = g_coef[bn*8+3] + b2_2[0], c4 = g_coef[bn*8+4] + b2_2[1], c5 = g_coef[bn*8+5] + b2_2[2];
    float c6 = g_coef[bn*8+6] + b2_3[0];
    #pragma unroll 4
    for (int fi = 0; fi < FCHUNK; fi++) {
        int f = f0 + fi;
        float tt = (float)f * (1.f/719.f);
        float t2 = tt*tt, t3 = t2*tt;
        float p0 = c0 + 0.5f*tt;
        float p1 = c1 + c2*tt + 0.5f*t2;
        float p2 = c3 + c4*tt + c5*t2 + 0.5f*t3;
        float p3 = c6 - 0.5f*tt;
        out[((long)b*Fc + f)*Nch + n] = w0*p0 + w1*p1 + w2*p2 + w3*p3;
    }
}

// ---------------- launch ----------------
extern "C" void kernel_launch(void* const* d_in, const int* in_sizes, int n_in,
                              void* d_out, int out_size)
{
    const float* x     = (const float*)d_in[0];
    const float* eps   = (const float*)d_in[1];
    const float* muW1  = (const float*)d_in[2];
    const float* mub1  = (const float*)d_in[3];
    const float* muW2  = (const float*)d_in[4];
    const float* mub2  = (const float*)d_in[5];
    const float* sgW1  = (const float*)d_in[6];
    const float* sgb1  = (const float*)d_in[7];
    const float* sgW2  = (const float*)d_in[8];
    const float* sgb2  = (const float*)d_in[9];
    const float* wgW1  = (const float*)d_in[10];
    const float* wgb1  = (const float*)d_in[11];
    const float* wgW2  = (const float*)d_in[12];
    // d_in[13] = wgb2 (cancels in softmax)
    const float* fb2[4] = {(const float*)d_in[17], (const float*)d_in[21],
                           (const float*)d_in[25], (const float*)d_in[29]};
    float* out = (float*)d_out;

    float* ms;  cudaGetSymbolAddress((void**)&ms,  g_ms);
    float* spm; cudaGetSymbolAddress((void**)&spm, g_spmu);
    float* sps; cudaGetSymbolAddress((void**)&sps, g_spsg);
    float* gw;  cudaGetSymbolAddress((void**)&gw,  g_w);
    float* cf;  cudaGetSymbolAddress((void**)&cf,  g_coef);
    float* Sp;  cudaGetSymbolAddress((void**)&Sp,  g_S);

    MainArgs a;
    a.wgW1 = wgW1; a.wgb1 = wgb1; a.wgW2 = wgW2;
    a.Sp = Sp; a.spm = spm; a.sps = sps; a.gw = gw; a.cf = cf;
    a.fW1[0] = (const float*)d_in[14]; a.fb1[0] = (const float*)d_in[15]; a.fW2[0] = (const float*)d_in[16];
    a.fW1[1] = (const float*)d_in[18]; a.fb1[1] = (const float*)d_in[19]; a.fW2[1] = (const float*)d_in[20];
    a.fW1[2] = (const float*)d_in[22]; a.fb1[2] = (const float*)d_in[23]; a.fW2[2] = (const float*)d_in[24];
    a.fW1[3] = (const float*)d_in[26]; a.fb1[3] = (const float*)d_in[27]; a.fW2[3] = (const float*)d_in[28];

    RowArgs ra;
    ra.wg = wgW1;
    for (int i = 0; i < 4; i++) ra.f[i] = a.fW1[i];

    // smem: NT=128/RT=3: 2*(14336+14336) + 5*128*4 + 2048 = 61952
    //       NT=64 /RT=4: 2*(14336+7168)  + 6*64*4  + 2048 = 46592
    const int SMEM_MAIN  = 61952;
    const int SMEM_MUSIG = 46592;
    static bool attr_set = false;
    if (!attr_set){
        cudaFuncSetAttribute(main_k,  cudaFuncAttributeMaxDynamicSharedMemorySize, SMEM_MAIN);
        cudaFuncSetAttribute(musig_k, cudaFuncAttributeMaxDynamicSharedMemorySize, SMEM_MUSIG);
        attr_set = true;
    }

    // rowsums (all 2944 rows in one launch)
    rowsum_all<<<(2944*32 + 255)/256, 256>>>(ra, Sp);

    // mu / sigma second-layer raw sums
    {
        dim3 grid(BNT/128, 2);
        musig_k<<<grid, NTHR, SMEM_MUSIG>>>(x, muW1, mub1, muW2, sgW1, sgb1, sgW2, ms);
    }
    softplus_k<<<(BNT*4 + 255)/256, 256>>>(mub2, sgb2);

    // fitters (512 CTAs, first) + wg (512 CTAs) in one launch
    main_k<<<1024, NTHR, SMEM_MAIN>>>(eps, a);

    // final mixture + transpose
    {
        dim3 grid(Fc/FCHUNK, Bc);
        final_kernel<<<grid, 128>>>(out, fb2[0], fb2[1], fb2[2], fb2[3]);
    }
}